// round 15
// baseline (speedup 1.0000x reference)
#include <cuda_runtime.h>
#include <cuda_fp16.h>
#include <math.h>
#include <stdint.h>

#define NN    100000
#define EMAX  3200000
#define F_IN  512
#define H1    64
#define H2    128
#define NC    40
#define BN_EPS 1e-5f
#define SCAN_B 512
#define NB    ((NN + SCAN_B - 1) / SCAN_B)

// ---------------- scratch (device globals; no allocation allowed) ----------
__device__ __align__(16) float  g_dinv[NN];
__device__ __align__(16) int    g_cnt[NN];
__device__ __align__(16) int    g_rowstart[NN + 1];
__device__ __align__(16) int    g_cursor[NN];
__device__ __align__(16) int    g_perm[EMAX];
__device__ __align__(16) int    g_part[NB];
__device__ __align__(16) int    g_order[NN];     // nodes sorted by degree
__device__ __align__(16) int    g_bins[256];     // degree histogram / cursors
__device__ int g_is64;
__device__ __align__(16) __half g_h1[(size_t)NN * 64];   // hs1*dinv / agg2 (fp16)
__device__ __align__(16) __half g_h2[(size_t)NN * 64];   // hs2 (fp16)
__device__ __align__(16) __half g_hC[(size_t)NN * 128];  // h2 (fp16)
__device__ __align__(16) __half g_h3[(size_t)NN * 40];   // hs3 (fp16)

// ---------------- CSR build --------------------------------------------------
__global__ void detect_k(const void* ei, int* flag) {
    if (threadIdx.x == 0) {
        const long long* p = (const long long*)ei;
        int is64 = 1;
        #pragma unroll
        for (int i = 0; i < 32; i++) {
            long long v = p[i];
            if (v < 0 || v >= NN) is64 = 0;
        }
        *flag = is64;
    }
}

__global__ void zero_i_k(int* p, int n) {
    int i = blockIdx.x * blockDim.x + threadIdx.x;
    if (i < n) p[i] = 0;
}

__global__ void prep_k(const void* eiv, int* __restrict__ cnt, int E,
                       const int* __restrict__ flag) {
    int e = blockIdx.x * blockDim.x + threadIdx.x;
    if (e >= E) return;
    int d;
    if (*flag) {
        d = (int)__ldg(&((const long long*)eiv)[(size_t)E + e]);
    } else {
        d = __ldg(&((const int*)eiv)[(size_t)E + e]);
    }
    d = min(max(d, 0), NN - 1);
    atomicAdd(&cnt[d], 1);
}

__global__ void scan1_k(const int* __restrict__ cnt, int* __restrict__ part, int n) {
    __shared__ int sh[SCAN_B];
    int i = blockIdx.x * SCAN_B + threadIdx.x;
    sh[threadIdx.x] = (i < n) ? cnt[i] : 0;
    __syncthreads();
    #pragma unroll
    for (int o = SCAN_B / 2; o > 0; o >>= 1) {
        if (threadIdx.x < o) sh[threadIdx.x] += sh[threadIdx.x + o];
        __syncthreads();
    }
    if (threadIdx.x == 0) part[blockIdx.x] = sh[0];
}

__global__ void scan2_k(int* part, int nb) {
    __shared__ int sh[256];
    int v = (threadIdx.x < nb) ? part[threadIdx.x] : 0;
    sh[threadIdx.x] = v;
    __syncthreads();
    #pragma unroll
    for (int o = 1; o < 256; o <<= 1) {
        int t = (threadIdx.x >= o) ? sh[threadIdx.x - o] : 0;
        __syncthreads();
        sh[threadIdx.x] += t;
        __syncthreads();
    }
    if (threadIdx.x < nb) part[threadIdx.x] = sh[threadIdx.x] - v;  // exclusive
}

__global__ void scan3_k(const int* __restrict__ cnt, const int* __restrict__ part,
                        int* __restrict__ rowstart, int* __restrict__ cursor,
                        float* __restrict__ dinv, int n) {
    __shared__ int sh[SCAN_B];
    int i = blockIdx.x * SCAN_B + threadIdx.x;
    int v = (i < n) ? cnt[i] : 0;
    sh[threadIdx.x] = v;
    __syncthreads();
    #pragma unroll
    for (int o = 1; o < SCAN_B; o <<= 1) {
        int t = (threadIdx.x >= o) ? sh[threadIdx.x - o] : 0;
        __syncthreads();
        sh[threadIdx.x] += t;
        __syncthreads();
    }
    int incl = sh[threadIdx.x];
    int off = part[blockIdx.x];
    if (i < n) {
        int excl = off + incl - v;
        rowstart[i] = excl;
        cursor[i] = excl;
        dinv[i] = rsqrtf((float)v + 1.0f);   // +1 self-loop
        if (i == n - 1) rowstart[n] = off + incl;
    }
}

__global__ void fill_k(const void* eiv, int* __restrict__ cursor,
                       int* __restrict__ perm, int E,
                       const int* __restrict__ flag) {
    int e = blockIdx.x * blockDim.x + threadIdx.x;
    if (e >= E) return;
    int s, d;
    if (*flag) {
        const long long* p64 = (const long long*)eiv;
        s = (int)__ldg(&p64[e]);
        d = (int)__ldg(&p64[(size_t)E + e]);
    } else {
        const int* p32 = (const int*)eiv;
        s = __ldg(&p32[e]);
        d = __ldg(&p32[(size_t)E + e]);
    }
    s = min(max(s, 0), NN - 1);
    d = min(max(d, 0), NN - 1);
    int pos = atomicAdd(&cursor[d], 1);
    pos = min(max(pos, 0), E - 1);
    perm[pos] = s;
}

// ---------------- degree-bucket counting sort (256 bins) --------------------
__global__ void hist_k(const int* __restrict__ cnt, int* __restrict__ bins, int n) {
    int i = blockIdx.x * blockDim.x + threadIdx.x;
    if (i < n) atomicAdd(&bins[min(cnt[i], 255)], 1);
}

__global__ void binscan_k(int* bins) {
    __shared__ int sh[256];
    int v = bins[threadIdx.x];
    sh[threadIdx.x] = v;
    __syncthreads();
    #pragma unroll
    for (int o = 1; o < 256; o <<= 1) {
        int t = (threadIdx.x >= o) ? sh[threadIdx.x - o] : 0;
        __syncthreads();
        sh[threadIdx.x] += t;
        __syncthreads();
    }
    bins[threadIdx.x] = sh[threadIdx.x] - v;   // exclusive offsets (reused as cursors)
}

__global__ void order_k(const int* __restrict__ cnt, int* __restrict__ bins,
                        int* __restrict__ order, int n) {
    int i = blockIdx.x * blockDim.x + threadIdx.x;
    if (i >= n) return;
    int b = min(cnt[i], 255);
    int pos = atomicAdd(&bins[b], 1);
    pos = min(max(pos, 0), n - 1);
    order[pos] = i;
}

// ---------------- h1 *= dinv[row]  (fp16 storage, fp32 math) ----------------
__global__ void scale1_k(__half* __restrict__ h, const float* __restrict__ dinv, int n) {
    int t = blockIdx.x * blockDim.x + threadIdx.x;       // n*8 threads
    if (t >= n * 8) return;
    int node = t >> 3;
    int seg  = t & 7;
    float dv = dinv[node];
    uint4 u = *reinterpret_cast<uint4*>(h + (size_t)node * 64 + seg * 8);
    uint32_t* w = &u.x;
    #pragma unroll
    for (int i = 0; i < 4; i++) {
        float2 f = __half22float2(*reinterpret_cast<__half2*>(&w[i]));
        __half2 r = __floats2half2_rn(f.x * dv, f.y * dv);
        w[i] = *reinterpret_cast<uint32_t*>(&r);
    }
    *reinterpret_cast<uint4*>(h + (size_t)node * 64 + seg * 8) = u;
}

// ---------------- warp-per-node gather aggregation (fp16 in, fp32 accum) ----
// warp -> node via degree-sorted order (load balance across co-resident warps)
__device__ __forceinline__ float4 ld_h4(const __half* p) {
    uint2 u = *reinterpret_cast<const uint2*>(p);
    float2 f01 = __half22float2(*reinterpret_cast<const __half2*>(&u.x));
    float2 f23 = __half22float2(*reinterpret_cast<const __half2*>(&u.y));
    return make_float4(f01.x, f01.y, f23.x, f23.y);
}

// EPI 0: out(fp16) = (sum + own) * dinv
// EPI 1: out(fp16) = relu(bn((sum + own)*dinv + b)) * dinv
// EPI 2: out(fp32) = log_softmax((sum + own)*dinv + b)   (D == 40)
template <int D, int EPI>
__global__ void __launch_bounds__(256) agg_k(
    const __half* __restrict__ hs, void* __restrict__ outv,
    const int* __restrict__ rowstart, const int* __restrict__ perm,
    const int* __restrict__ order, const float* __restrict__ dinv,
    const float* __restrict__ b, const float* __restrict__ g,
    const float* __restrict__ bt, const float* __restrict__ rm,
    const float* __restrict__ rv, int n) {
    const int warp = (blockIdx.x * blockDim.x + threadIdx.x) >> 5;
    const int lane = threadIdx.x & 31;
    if (warp >= n) return;
    const int node = __ldg(&order[warp]);
    const int half = lane >> 4;          // 0 or 1
    const int hl   = lane & 15;
    const int c    = hl * 4;
    const bool act = (c < D);
    const int start = __ldg(&rowstart[node]);
    const int end   = __ldg(&rowstart[node + 1]);

    float sx = 0.f, sy = 0.f, sz = 0.f, sw = 0.f;
    int j = start + half;
    for (; j + 2 < end; j += 4) {
        int s0 = __ldg(&perm[j]);
        int s1 = __ldg(&perm[j + 2]);
        if (act) {
            float4 v0 = ld_h4(hs + (size_t)s0 * D + c);
            float4 v1 = ld_h4(hs + (size_t)s1 * D + c);
            sx += v0.x + v1.x;
            sy += v0.y + v1.y;
            sz += v0.z + v1.z;
            sw += v0.w + v1.w;
        }
    }
    if (j < end) {
        int s0 = __ldg(&perm[j]);
        if (act) {
            float4 v0 = ld_h4(hs + (size_t)s0 * D + c);
            sx += v0.x; sy += v0.y; sz += v0.z; sw += v0.w;
        }
    }
    sx += __shfl_xor_sync(0xffffffffu, sx, 16);
    sy += __shfl_xor_sync(0xffffffffu, sy, 16);
    sz += __shfl_xor_sync(0xffffffffu, sz, 16);
    sw += __shfl_xor_sync(0xffffffffu, sw, 16);

    const float dv = __ldg(&dinv[node]);
    float4 own = act ? ld_h4(hs + (size_t)node * D + c)
                     : make_float4(0.f, 0.f, 0.f, 0.f);
    float vx = (sx + own.x) * dv;
    float vy = (sy + own.y) * dv;
    float vz = (sz + own.z) * dv;
    float vw = (sw + own.w) * dv;

    if (EPI == 1) {
        if (half == 0 && act) {
            float4 bb  = __ldg(reinterpret_cast<const float4*>(b + c));
            float4 gg  = __ldg(reinterpret_cast<const float4*>(g + c));
            float4 bt4 = __ldg(reinterpret_cast<const float4*>(bt + c));
            float4 rm4 = __ldg(reinterpret_cast<const float4*>(rm + c));
            float4 rv4 = __ldg(reinterpret_cast<const float4*>(rv + c));
            vx = fmaxf((vx + bb.x - rm4.x) * (gg.x * rsqrtf(rv4.x + BN_EPS)) + bt4.x, 0.f) * dv;
            vy = fmaxf((vy + bb.y - rm4.y) * (gg.y * rsqrtf(rv4.y + BN_EPS)) + bt4.y, 0.f) * dv;
            vz = fmaxf((vz + bb.z - rm4.z) * (gg.z * rsqrtf(rv4.z + BN_EPS)) + bt4.z, 0.f) * dv;
            vw = fmaxf((vw + bb.w - rm4.w) * (gg.w * rsqrtf(rv4.w + BN_EPS)) + bt4.w, 0.f) * dv;
            __half2 o01 = __floats2half2_rn(vx, vy);
            __half2 o23 = __floats2half2_rn(vz, vw);
            uint2 u;
            u.x = *reinterpret_cast<uint32_t*>(&o01);
            u.y = *reinterpret_cast<uint32_t*>(&o23);
            *reinterpret_cast<uint2*>((__half*)outv + (size_t)node * D + c) = u;
        }
    } else if (EPI == 0) {
        if (half == 0 && act) {
            __half2 o01 = __floats2half2_rn(vx, vy);
            __half2 o23 = __floats2half2_rn(vz, vw);
            uint2 u;
            u.x = *reinterpret_cast<uint32_t*>(&o01);
            u.y = *reinterpret_cast<uint32_t*>(&o23);
            *reinterpret_cast<uint2*>((__half*)outv + (size_t)node * D + c) = u;
        }
    } else {
        float4 bb = act ? __ldg(reinterpret_cast<const float4*>(b + c))
                        : make_float4(0.f, 0.f, 0.f, 0.f);
        vx += bb.x; vy += bb.y; vz += bb.z; vw += bb.w;
        float m = act ? fmaxf(fmaxf(vx, vy), fmaxf(vz, vw)) : -INFINITY;
        #pragma unroll
        for (int o = 8; o; o >>= 1) m = fmaxf(m, __shfl_xor_sync(0xffffffffu, m, o));
        float es = act ? (expf(vx - m) + expf(vy - m) + expf(vz - m) + expf(vw - m)) : 0.f;
        #pragma unroll
        for (int o = 8; o; o >>= 1) es += __shfl_xor_sync(0xffffffffu, es, o);
        float lse = m + logf(es);
        if (half == 0 && act)
            *reinterpret_cast<float4*>((float*)outv + (size_t)node * D + c) =
                make_float4(vx - lse, vy - lse, vz - lse, vw - lse);
    }
}

// ---------------- tensor-core GEMM: tf32 single-pass, fp32 accum ------------
__device__ __forceinline__ void mma_tf32(float* c, const uint32_t* a, const uint32_t* b) {
    asm volatile(
        "mma.sync.aligned.m16n8k8.row.col.f32.tf32.tf32.f32 "
        "{%0,%1,%2,%3}, {%4,%5,%6,%7}, {%8,%9}, {%0,%1,%2,%3};"
        : "+f"(c[0]), "+f"(c[1]), "+f"(c[2]), "+f"(c[3])
        : "r"(a[0]), "r"(a[1]), "r"(a[2]), "r"(a[3]), "r"(b[0]), "r"(b[1]));
}

template <int EPI, bool OUTH, bool INH>
__global__ void __launch_bounds__(256) gemm_tf32_k(
    const void* __restrict__ Av, const float* __restrict__ W,
    void* __restrict__ Cv, int M, int N, int K,
    const float* __restrict__ p0, const float* __restrict__ p1,
    const float* __restrict__ p2, const float* __restrict__ p3,
    const float* __restrict__ p4, const float* __restrict__ p5) {
    constexpr int SA = 36;
    constexpr int SB = 36;
    __shared__ __align__(16) float As[128 * SA];
    __shared__ __align__(16) float Bs[64 * SB];

    const int tid  = threadIdx.x;
    const int lane = tid & 31;
    const int warp = tid >> 5;
    const int gqp  = lane >> 2;
    const int tig  = lane & 3;
    const int wm   = warp >> 1;
    const int wn   = warp & 1;
    const int row0 = blockIdx.x * 128;
    const int col0 = blockIdx.y * 64;

    float acc[2][4][4];
    #pragma unroll
    for (int mi = 0; mi < 2; mi++)
        #pragma unroll
        for (int ni = 0; ni < 4; ni++)
            #pragma unroll
            for (int q = 0; q < 4; q++) acc[mi][ni][q] = 0.f;

    for (int k0 = 0; k0 < K; k0 += 32) {
        #pragma unroll
        for (int i = 0; i < 4; i++) {
            int li = tid + i * 256;
            int r  = li >> 3;
            int kc = (li & 7) * 4;
            int grow = row0 + r;
            float4 v;
            if (grow < M) {
                if (INH) {
                    const __half* Ah_ = (const __half*)Av;
                    uint2 u = __ldg(reinterpret_cast<const uint2*>(
                        Ah_ + (size_t)grow * K + k0 + kc));
                    float2 f01 = __half22float2(*reinterpret_cast<const __half2*>(&u.x));
                    float2 f23 = __half22float2(*reinterpret_cast<const __half2*>(&u.y));
                    v = make_float4(f01.x, f01.y, f23.x, f23.y);
                } else {
                    const float* Af_ = (const float*)Av;
                    v = __ldg(reinterpret_cast<const float4*>(
                        Af_ + (size_t)grow * K + k0 + kc));
                }
            } else {
                v = make_float4(0.f, 0.f, 0.f, 0.f);
            }
            *reinterpret_cast<float4*>(&As[r * SA + kc]) = v;
        }
        #pragma unroll
        for (int i = 0; i < 8; i++) {
            int li = tid + i * 256;
            int kk = li >> 6;
            int nn = li & 63;
            float v = (col0 + nn < N) ? __ldg(&W[(size_t)(k0 + kk) * N + col0 + nn]) : 0.f;
            Bs[nn * SB + kk] = v;
        }
        __syncthreads();

        #pragma unroll
        for (int ks = 0; ks < 32; ks += 8) {
            uint32_t af[2][4];
            #pragma unroll
            for (int mi = 0; mi < 2; mi++) {
                int r = wm * 32 + mi * 16 + gqp;
                af[mi][0] = __float_as_uint(As[r * SA + ks + tig]);
                af[mi][1] = __float_as_uint(As[(r + 8) * SA + ks + tig]);
                af[mi][2] = __float_as_uint(As[r * SA + ks + tig + 4]);
                af[mi][3] = __float_as_uint(As[(r + 8) * SA + ks + tig + 4]);
            }
            uint32_t bf[4][2];
            #pragma unroll
            for (int ni = 0; ni < 4; ni++) {
                int nr = wn * 32 + ni * 8 + gqp;
                bf[ni][0] = __float_as_uint(Bs[nr * SB + ks + tig]);
                bf[ni][1] = __float_as_uint(Bs[nr * SB + ks + tig + 4]);
            }
            #pragma unroll
            for (int mi = 0; mi < 2; mi++)
                #pragma unroll
                for (int ni = 0; ni < 4; ni++)
                    mma_tf32(acc[mi][ni], af[mi], bf[ni]);
        }
        __syncthreads();
    }

    #pragma unroll
    for (int ni = 0; ni < 4; ni++) {
        int cb = col0 + wn * 32 + ni * 8 + 2 * tig;
        float sc0 = 1.f, of0 = 0.f, sc1 = 1.f, of1 = 0.f;
        if (EPI == 1) {
            if (cb < N) {
                float s = p2[cb] * rsqrtf(p5[cb] + BN_EPS);
                sc0 = s; of0 = (p1[cb] - p4[cb]) * s + p3[cb];
            }
            if (cb + 1 < N) {
                float s = p2[cb + 1] * rsqrtf(p5[cb + 1] + BN_EPS);
                sc1 = s; of1 = (p1[cb + 1] - p4[cb + 1]) * s + p3[cb + 1];
            }
        }
        #pragma unroll
        for (int mi = 0; mi < 2; mi++) {
            #pragma unroll
            for (int rr = 0; rr < 2; rr++) {
                int r = row0 + wm * 32 + mi * 16 + gqp + rr * 8;
                if (r >= M) continue;
                float v0 = acc[mi][ni][rr * 2 + 0];
                float v1 = acc[mi][ni][rr * 2 + 1];
                if (EPI == 0) {
                    float dv = p0[r];
                    v0 *= dv; v1 *= dv;
                } else if (EPI == 1) {
                    v0 = fmaxf(v0 * sc0 + of0, 0.f);
                    v1 = fmaxf(v1 * sc1 + of1, 0.f);
                }
                if (OUTH) {
                    __half* C = (__half*)Cv;
                    if (cb + 1 < N)
                        *reinterpret_cast<__half2*>(C + (size_t)r * N + cb) = __floats2half2_rn(v0, v1);
                    else if (cb < N)
                        C[(size_t)r * N + cb] = __float2half_rn(v0);
                } else {
                    float* C = (float*)Cv;
                    if (cb + 1 < N)
                        *reinterpret_cast<float2*>(C + (size_t)r * N + cb) = make_float2(v0, v1);
                    else if (cb < N)
                        C[(size_t)r * N + cb] = v0;
                }
            }
        }
    }
}

// ---------------- launch ----------------------------------------------------
extern "C" void kernel_launch(void* const* d_in, const int* in_sizes, int n_in,
                              void* d_out, int out_size) {
    const float* x   = (const float*)d_in[0];
    const void*  ei  = d_in[1];
    const float* W1  = (const float*)d_in[2];
    const float* b1  = (const float*)d_in[3];
    const float* W2  = (const float*)d_in[4];
    const float* b2  = (const float*)d_in[5];
    const float* W3  = (const float*)d_in[6];
    const float* b3  = (const float*)d_in[7];
    const float* g1  = (const float*)d_in[8];
    const float* bt1 = (const float*)d_in[9];
    const float* rm1 = (const float*)d_in[10];
    const float* rv1 = (const float*)d_in[11];
    const float* g2  = (const float*)d_in[12];
    const float* bt2 = (const float*)d_in[13];
    const float* rm2 = (const float*)d_in[14];
    const float* rv2 = (const float*)d_in[15];
    float* out = (float*)d_out;
    const int E = in_sizes[1] / 2;
    const int n = NN;

    float *pDinv;
    __half *pH1, *pH2, *pHC, *pH3;
    int *pCnt, *pRow, *pCur, *pPerm, *pPart, *pFlag, *pOrder, *pBins;
    cudaGetSymbolAddress((void**)&pDinv,  g_dinv);
    cudaGetSymbolAddress((void**)&pCnt,   g_cnt);
    cudaGetSymbolAddress((void**)&pRow,   g_rowstart);
    cudaGetSymbolAddress((void**)&pCur,   g_cursor);
    cudaGetSymbolAddress((void**)&pPerm,  g_perm);
    cudaGetSymbolAddress((void**)&pPart,  g_part);
    cudaGetSymbolAddress((void**)&pFlag,  g_is64);
    cudaGetSymbolAddress((void**)&pOrder, g_order);
    cudaGetSymbolAddress((void**)&pBins,  g_bins);
    cudaGetSymbolAddress((void**)&pH1,    g_h1);
    cudaGetSymbolAddress((void**)&pH2,    g_h2);
    cudaGetSymbolAddress((void**)&pHC,    g_hC);
    cudaGetSymbolAddress((void**)&pH3,    g_h3);

    static cudaStream_t s2 = 0, s3 = 0;
    static cudaEvent_t evF = 0, evP = 0, evJ = 0, evO = 0;
    if (s2 == 0) {
        if (cudaStreamCreateWithFlags(&s2, cudaStreamNonBlocking) != cudaSuccess) s2 = 0;
        if (s2 && cudaStreamCreateWithFlags(&s3, cudaStreamNonBlocking) != cudaSuccess) {
            s3 = 0;
        }
        if (s2) {
            cudaEventCreateWithFlags(&evF, cudaEventDisableTiming);
            cudaEventCreateWithFlags(&evP, cudaEventDisableTiming);
            cudaEventCreateWithFlags(&evJ, cudaEventDisableTiming);
            cudaEventCreateWithFlags(&evO, cudaEventDisableTiming);
        }
    }
    const bool dual = (s2 != 0);
    const bool tri  = dual && (s3 != 0);
    cudaStream_t sc = dual ? s2 : (cudaStream_t)0;
    cudaStream_t so = tri ? s3 : sc;

    const int T = 256;

    // ---- fork: CSR build on side stream(s) ----
    if (dual) {
        cudaEventRecord(evF, 0);
        cudaStreamWaitEvent(s2, evF, 0);
        if (tri) cudaStreamWaitEvent(s3, evF, 0);
    }
    detect_k<<<1, 32, 0, sc>>>(ei, pFlag);
    zero_i_k<<<(n + T - 1) / T, T, 0, sc>>>(pCnt, n);
    zero_i_k<<<1, 256, 0, so>>>(pBins, 256);
    prep_k<<<(E + T - 1) / T, T, 0, sc>>>(ei, pCnt, E, pFlag);
    if (dual) {
        cudaEventRecord(evP, s2);                   // cnt ready
        if (tri) cudaStreamWaitEvent(s3, evP, 0);
    }
    // CSR chain continues on s2
    scan1_k<<<NB, SCAN_B, 0, sc>>>(pCnt, pPart, n);
    scan2_k<<<1, 256, 0, sc>>>(pPart, NB);
    scan3_k<<<NB, SCAN_B, 0, sc>>>(pCnt, pPart, pRow, pCur, pDinv, n);
    fill_k<<<(E + T - 1) / T, T, 0, sc>>>(ei, pCur, pPerm, E, pFlag);
    if (dual) cudaEventRecord(evJ, s2);
    // degree sort on s3 (or same stream if s3 unavailable)
    hist_k<<<(n + T - 1) / T, T, 0, so>>>(pCnt, pBins, n);
    binscan_k<<<1, 256, 0, so>>>(pBins);
    order_k<<<(n + T - 1) / T, T, 0, so>>>(pCnt, pBins, pOrder, n);
    if (tri) cudaEventRecord(evO, s3);

    // ---- layer 1 (overlapped with CSR): hs1_raw = x @ W1 -> fp16 ----
    gemm_tf32_k<2, true, false><<<dim3((n + 127) / 128, 1), 256>>>(
        x, W1, pH1, n, H1, F_IN, nullptr, nullptr, nullptr, nullptr, nullptr, nullptr);

    // ---- join ----
    if (dual) {
        cudaStreamWaitEvent(0, evJ, 0);
        if (tri) cudaStreamWaitEvent(0, evO, 0);
    }

    // h1 *= dinv[row]
    scale1_k<<<(n * 8 + T - 1) / T, T>>>(pH1, pDinv, n);

    // hs2(fp16) = relu(bn1(agg(h1') + b1)) * dinv
    agg_k<64, 1><<<(n * 32 + T - 1) / T, T>>>(pH1, pH2, pRow, pPerm, pOrder, pDinv,
                                              b1, g1, bt1, rm1, rv1, n);

    // ---- layer 2: agg2(fp16, reuses g_h1) ----
    agg_k<64, 0><<<(n * 32 + T - 1) / T, T>>>(pH2, pH1, pRow, pPerm, pOrder, pDinv,
                                              nullptr, nullptr, nullptr, nullptr, nullptr, n);
    // h2(fp16) = relu(bn2(agg2 @ W2 + b2))
    gemm_tf32_k<1, true, true><<<dim3((n + 127) / 128, 2), 256>>>(
        pH1, W2, pHC, n, H2, H1, nullptr, b2, g2, bt2, rm2, rv2);

    // ---- layer 3: hs3(fp16) = (h2 @ W3) * dinv ----
    gemm_tf32_k<0, true, true><<<dim3((n + 127) / 128, 1), 256>>>(
        pHC, W3, pH3, n, NC, H2, pDinv, nullptr, nullptr, nullptr, nullptr, nullptr);

    // agg3 + b3 + log_softmax fused, writes d_out directly
    agg_k<40, 2><<<(n * 32 + T - 1) / T, T>>>(pH3, out, pRow, pPerm, pOrder, pDinv,
                                              b3, nullptr, nullptr, nullptr, nullptr, n);
}

// round 16
// speedup vs baseline: 1.0973x; 1.0973x over previous
#include <cuda_runtime.h>
#include <cuda_fp16.h>
#include <math.h>
#include <stdint.h>

#define NN    100000
#define EMAX  3200000
#define F_IN  512
#define H1    64
#define H2    128
#define NC    40
#define BN_EPS 1e-5f
#define SCAN_B 512
#define NB    ((NN + SCAN_B - 1) / SCAN_B)

// ---------------- scratch (device globals; no allocation allowed) ----------
__device__ __align__(16) float  g_dinv[NN];
__device__ __align__(16) int    g_cnt[NN];
__device__ __align__(16) int    g_rowstart[NN + 1];
__device__ __align__(16) int    g_cursor[NN];
__device__ __align__(16) int    g_perm[EMAX];
__device__ __align__(16) int    g_part[NB];
__device__ int g_is64;
__device__ __align__(16) __half g_h1[(size_t)NN * 64];   // hs1*dinv / agg2 (fp16)
__device__ __align__(16) __half g_h2[(size_t)NN * 64];   // hs2 (fp16)
__device__ __align__(16) __half g_hC[(size_t)NN * 128];  // h2 (fp16)
__device__ __align__(16) __half g_h3[(size_t)NN * 40];   // hs3 (fp16)

// ---------------- CSR build --------------------------------------------------
__global__ void detect_k(const void* ei, int* flag) {
    if (threadIdx.x == 0) {
        const long long* p = (const long long*)ei;
        int is64 = 1;
        #pragma unroll
        for (int i = 0; i < 32; i++) {
            long long v = p[i];
            if (v < 0 || v >= NN) is64 = 0;
        }
        *flag = is64;
    }
}

__global__ void zero_i_k(int* p, int n) {
    int i = blockIdx.x * blockDim.x + threadIdx.x;
    if (i < n) p[i] = 0;
}

// count in-degree: 4 edges per thread (vectorized when E aligned)
__global__ void prep_k(const void* eiv, int* __restrict__ cnt, int E,
                       const int* __restrict__ flag) {
    int t = blockIdx.x * blockDim.x + threadIdx.x;
    int e0 = t * 4;
    if (e0 >= E) return;
    int d[4];
    int m = min(4, E - e0);
    if (*flag) {
        const long long* p64 = (const long long*)eiv + (size_t)E;
        if (m == 4 && ((E & 1) == 0)) {
            longlong2 a = __ldg(reinterpret_cast<const longlong2*>(p64 + e0));
            longlong2 b = __ldg(reinterpret_cast<const longlong2*>(p64 + e0 + 2));
            d[0] = (int)a.x; d[1] = (int)a.y; d[2] = (int)b.x; d[3] = (int)b.y;
        } else {
            for (int i = 0; i < m; i++) d[i] = (int)__ldg(&p64[e0 + i]);
        }
    } else {
        const int* p32 = (const int*)eiv + (size_t)E;
        if (m == 4 && ((E & 3) == 0)) {
            int4 a = __ldg(reinterpret_cast<const int4*>(p32 + e0));
            d[0] = a.x; d[1] = a.y; d[2] = a.z; d[3] = a.w;
        } else {
            for (int i = 0; i < m; i++) d[i] = __ldg(&p32[e0 + i]);
        }
    }
    #pragma unroll
    for (int i = 0; i < 4; i++) {
        if (i < m) {
            int dd = min(max(d[i], 0), NN - 1);
            atomicAdd(&cnt[dd], 1);
        }
    }
}

__global__ void scan1_k(const int* __restrict__ cnt, int* __restrict__ part, int n) {
    __shared__ int sh[SCAN_B];
    int i = blockIdx.x * SCAN_B + threadIdx.x;
    sh[threadIdx.x] = (i < n) ? cnt[i] : 0;
    __syncthreads();
    #pragma unroll
    for (int o = SCAN_B / 2; o > 0; o >>= 1) {
        if (threadIdx.x < o) sh[threadIdx.x] += sh[threadIdx.x + o];
        __syncthreads();
    }
    if (threadIdx.x == 0) part[blockIdx.x] = sh[0];
}

__global__ void scan2_k(int* part, int nb) {
    __shared__ int sh[256];
    int v = (threadIdx.x < nb) ? part[threadIdx.x] : 0;
    sh[threadIdx.x] = v;
    __syncthreads();
    #pragma unroll
    for (int o = 1; o < 256; o <<= 1) {
        int t = (threadIdx.x >= o) ? sh[threadIdx.x - o] : 0;
        __syncthreads();
        sh[threadIdx.x] += t;
        __syncthreads();
    }
    if (threadIdx.x < nb) part[threadIdx.x] = sh[threadIdx.x] - v;  // exclusive
}

__global__ void scan3_k(const int* __restrict__ cnt, const int* __restrict__ part,
                        int* __restrict__ rowstart, int* __restrict__ cursor,
                        float* __restrict__ dinv, int n) {
    __shared__ int sh[SCAN_B];
    int i = blockIdx.x * SCAN_B + threadIdx.x;
    int v = (i < n) ? cnt[i] : 0;
    sh[threadIdx.x] = v;
    __syncthreads();
    #pragma unroll
    for (int o = 1; o < SCAN_B; o <<= 1) {
        int t = (threadIdx.x >= o) ? sh[threadIdx.x - o] : 0;
        __syncthreads();
        sh[threadIdx.x] += t;
        __syncthreads();
    }
    int incl = sh[threadIdx.x];
    int off = part[blockIdx.x];
    if (i < n) {
        int excl = off + incl - v;
        rowstart[i] = excl;
        cursor[i] = excl;
        dinv[i] = rsqrtf((float)v + 1.0f);   // +1 self-loop
        if (i == n - 1) rowstart[n] = off + incl;
    }
}

// place src into CSR perm slots: 2 edges per thread (vectorized when aligned)
__global__ void fill_k(const void* eiv, int* __restrict__ cursor,
                       int* __restrict__ perm, int E,
                       const int* __restrict__ flag) {
    int t = blockIdx.x * blockDim.x + threadIdx.x;
    int e0 = t * 2;
    if (e0 >= E) return;
    int s[2], d[2];
    int m = min(2, E - e0);
    if (*flag) {
        const long long* p64 = (const long long*)eiv;
        if (m == 2 && ((E & 1) == 0)) {
            longlong2 a = __ldg(reinterpret_cast<const longlong2*>(p64 + e0));
            longlong2 b = __ldg(reinterpret_cast<const longlong2*>(p64 + (size_t)E + e0));
            s[0] = (int)a.x; s[1] = (int)a.y;
            d[0] = (int)b.x; d[1] = (int)b.y;
        } else {
            for (int i = 0; i < m; i++) {
                s[i] = (int)__ldg(&p64[e0 + i]);
                d[i] = (int)__ldg(&p64[(size_t)E + e0 + i]);
            }
        }
    } else {
        const int* p32 = (const int*)eiv;
        if (m == 2 && ((E & 1) == 0)) {
            int2 a = __ldg(reinterpret_cast<const int2*>(p32 + e0));
            int2 b = __ldg(reinterpret_cast<const int2*>(p32 + (size_t)E + e0));
            s[0] = a.x; s[1] = a.y;
            d[0] = b.x; d[1] = b.y;
        } else {
            for (int i = 0; i < m; i++) {
                s[i] = __ldg(&p32[e0 + i]);
                d[i] = __ldg(&p32[(size_t)E + e0 + i]);
            }
        }
    }
    #pragma unroll
    for (int i = 0; i < 2; i++) {
        if (i < m) {
            int ss = min(max(s[i], 0), NN - 1);
            int dd = min(max(d[i], 0), NN - 1);
            int pos = atomicAdd(&cursor[dd], 1);
            pos = min(max(pos, 0), E - 1);
            perm[pos] = ss;
        }
    }
}

// ---------------- h1 *= dinv[row]  (fp16 storage, fp32 math) ----------------
__global__ void scale1_k(__half* __restrict__ h, const float* __restrict__ dinv, int n) {
    int t = blockIdx.x * blockDim.x + threadIdx.x;       // n*8 threads
    if (t >= n * 8) return;
    int node = t >> 3;
    int seg  = t & 7;
    float dv = dinv[node];
    uint4 u = *reinterpret_cast<uint4*>(h + (size_t)node * 64 + seg * 8);
    uint32_t* w = &u.x;
    #pragma unroll
    for (int i = 0; i < 4; i++) {
        float2 f = __half22float2(*reinterpret_cast<__half2*>(&w[i]));
        __half2 r = __floats2half2_rn(f.x * dv, f.y * dv);
        w[i] = *reinterpret_cast<uint32_t*>(&r);
    }
    *reinterpret_cast<uint4*>(h + (size_t)node * 64 + seg * 8) = u;
}

// ---------------- warp-per-node gather aggregation (fp16 in, fp32 accum) ----
__device__ __forceinline__ float4 ld_h4(const __half* p) {
    uint2 u = *reinterpret_cast<const uint2*>(p);
    float2 f01 = __half22float2(*reinterpret_cast<const __half2*>(&u.x));
    float2 f23 = __half22float2(*reinterpret_cast<const __half2*>(&u.y));
    return make_float4(f01.x, f01.y, f23.x, f23.y);
}

// EPI 0: out(fp16) = (sum + own) * dinv
// EPI 1: out(fp16) = relu(bn((sum + own)*dinv + b)) * dinv
// EPI 2: out(fp32) = log_softmax((sum + own)*dinv + b)   (D == 40)
template <int D, int EPI>
__global__ void __launch_bounds__(256) agg_k(
    const __half* __restrict__ hs, void* __restrict__ outv,
    const int* __restrict__ rowstart, const int* __restrict__ perm,
    const float* __restrict__ dinv,
    const float* __restrict__ b, const float* __restrict__ g,
    const float* __restrict__ bt, const float* __restrict__ rm,
    const float* __restrict__ rv, int n) {
    const int warp = (blockIdx.x * blockDim.x + threadIdx.x) >> 5;
    const int lane = threadIdx.x & 31;
    if (warp >= n) return;
    const int node = warp;
    const int half = lane >> 4;          // 0 or 1
    const int hl   = lane & 15;
    const int c    = hl * 4;
    const bool act = (c < D);
    const int start = rowstart[node];
    const int end   = rowstart[node + 1];

    float sx = 0.f, sy = 0.f, sz = 0.f, sw = 0.f;
    int j = start + half;
    for (; j + 2 < end; j += 4) {
        int s0 = __ldg(&perm[j]);
        int s1 = __ldg(&perm[j + 2]);
        if (act) {
            float4 v0 = ld_h4(hs + (size_t)s0 * D + c);
            float4 v1 = ld_h4(hs + (size_t)s1 * D + c);
            sx += v0.x + v1.x;
            sy += v0.y + v1.y;
            sz += v0.z + v1.z;
            sw += v0.w + v1.w;
        }
    }
    if (j < end) {
        int s0 = __ldg(&perm[j]);
        if (act) {
            float4 v0 = ld_h4(hs + (size_t)s0 * D + c);
            sx += v0.x; sy += v0.y; sz += v0.z; sw += v0.w;
        }
    }
    sx += __shfl_xor_sync(0xffffffffu, sx, 16);
    sy += __shfl_xor_sync(0xffffffffu, sy, 16);
    sz += __shfl_xor_sync(0xffffffffu, sz, 16);
    sw += __shfl_xor_sync(0xffffffffu, sw, 16);

    const float dv = dinv[node];
    float4 own = act ? ld_h4(hs + (size_t)node * D + c)
                     : make_float4(0.f, 0.f, 0.f, 0.f);
    float vx = (sx + own.x) * dv;
    float vy = (sy + own.y) * dv;
    float vz = (sz + own.z) * dv;
    float vw = (sw + own.w) * dv;

    if (EPI == 1) {
        if (half == 0 && act) {
            float4 bb  = __ldg(reinterpret_cast<const float4*>(b + c));
            float4 gg  = __ldg(reinterpret_cast<const float4*>(g + c));
            float4 bt4 = __ldg(reinterpret_cast<const float4*>(bt + c));
            float4 rm4 = __ldg(reinterpret_cast<const float4*>(rm + c));
            float4 rv4 = __ldg(reinterpret_cast<const float4*>(rv + c));
            vx = fmaxf((vx + bb.x - rm4.x) * (gg.x * rsqrtf(rv4.x + BN_EPS)) + bt4.x, 0.f) * dv;
            vy = fmaxf((vy + bb.y - rm4.y) * (gg.y * rsqrtf(rv4.y + BN_EPS)) + bt4.y, 0.f) * dv;
            vz = fmaxf((vz + bb.z - rm4.z) * (gg.z * rsqrtf(rv4.z + BN_EPS)) + bt4.z, 0.f) * dv;
            vw = fmaxf((vw + bb.w - rm4.w) * (gg.w * rsqrtf(rv4.w + BN_EPS)) + bt4.w, 0.f) * dv;
            __half2 o01 = __floats2half2_rn(vx, vy);
            __half2 o23 = __floats2half2_rn(vz, vw);
            uint2 u;
            u.x = *reinterpret_cast<uint32_t*>(&o01);
            u.y = *reinterpret_cast<uint32_t*>(&o23);
            *reinterpret_cast<uint2*>((__half*)outv + (size_t)node * D + c) = u;
        }
    } else if (EPI == 0) {
        if (half == 0 && act) {
            __half2 o01 = __floats2half2_rn(vx, vy);
            __half2 o23 = __floats2half2_rn(vz, vw);
            uint2 u;
            u.x = *reinterpret_cast<uint32_t*>(&o01);
            u.y = *reinterpret_cast<uint32_t*>(&o23);
            *reinterpret_cast<uint2*>((__half*)outv + (size_t)node * D + c) = u;
        }
    } else {
        float4 bb = act ? __ldg(reinterpret_cast<const float4*>(b + c))
                        : make_float4(0.f, 0.f, 0.f, 0.f);
        vx += bb.x; vy += bb.y; vz += bb.z; vw += bb.w;
        float m = act ? fmaxf(fmaxf(vx, vy), fmaxf(vz, vw)) : -INFINITY;
        #pragma unroll
        for (int o = 8; o; o >>= 1) m = fmaxf(m, __shfl_xor_sync(0xffffffffu, m, o));
        float es = act ? (expf(vx - m) + expf(vy - m) + expf(vz - m) + expf(vw - m)) : 0.f;
        #pragma unroll
        for (int o = 8; o; o >>= 1) es += __shfl_xor_sync(0xffffffffu, es, o);
        float lse = m + logf(es);
        if (half == 0 && act)
            *reinterpret_cast<float4*>((float*)outv + (size_t)node * D + c) =
                make_float4(vx - lse, vy - lse, vz - lse, vw - lse);
    }
}

// ---------------- tensor-core GEMM: tf32 single-pass, fp32 accum ------------
// INH: A buffer is fp16 (converted to fp32 while staging into smem).
// EPI 0: C = acc * dinv[row]   EPI 1: C = relu(bn(acc + bias))   EPI 2: raw
// OUTH: write __half output, else fp32.
__device__ __forceinline__ void mma_tf32(float* c, const uint32_t* a, const uint32_t* b) {
    asm volatile(
        "mma.sync.aligned.m16n8k8.row.col.f32.tf32.tf32.f32 "
        "{%0,%1,%2,%3}, {%4,%5,%6,%7}, {%8,%9}, {%0,%1,%2,%3};"
        : "+f"(c[0]), "+f"(c[1]), "+f"(c[2]), "+f"(c[3])
        : "r"(a[0]), "r"(a[1]), "r"(a[2]), "r"(a[3]), "r"(b[0]), "r"(b[1]));
}

template <int EPI, bool OUTH, bool INH>
__global__ void __launch_bounds__(256) gemm_tf32_k(
    const void* __restrict__ Av, const float* __restrict__ W,
    void* __restrict__ Cv, int M, int N, int K,
    const float* __restrict__ p0, const float* __restrict__ p1,
    const float* __restrict__ p2, const float* __restrict__ p3,
    const float* __restrict__ p4, const float* __restrict__ p5) {
    constexpr int SA = 36;
    constexpr int SB = 36;
    __shared__ __align__(16) float As[128 * SA];
    __shared__ __align__(16) float Bs[64 * SB];

    const int tid  = threadIdx.x;
    const int lane = tid & 31;
    const int warp = tid >> 5;
    const int gqp  = lane >> 2;
    const int tig  = lane & 3;
    const int wm   = warp >> 1;
    const int wn   = warp & 1;
    const int row0 = blockIdx.x * 128;
    const int col0 = blockIdx.y * 64;

    float acc[2][4][4];
    #pragma unroll
    for (int mi = 0; mi < 2; mi++)
        #pragma unroll
        for (int ni = 0; ni < 4; ni++)
            #pragma unroll
            for (int q = 0; q < 4; q++) acc[mi][ni][q] = 0.f;

    for (int k0 = 0; k0 < K; k0 += 32) {
        #pragma unroll
        for (int i = 0; i < 4; i++) {
            int li = tid + i * 256;
            int r  = li >> 3;
            int kc = (li & 7) * 4;
            int grow = row0 + r;
            float4 v;
            if (grow < M) {
                if (INH) {
                    const __half* Ah_ = (const __half*)Av;
                    uint2 u = __ldg(reinterpret_cast<const uint2*>(
                        Ah_ + (size_t)grow * K + k0 + kc));
                    float2 f01 = __half22float2(*reinterpret_cast<const __half2*>(&u.x));
                    float2 f23 = __half22float2(*reinterpret_cast<const __half2*>(&u.y));
                    v = make_float4(f01.x, f01.y, f23.x, f23.y);
                } else {
                    const float* Af_ = (const float*)Av;
                    v = __ldg(reinterpret_cast<const float4*>(
                        Af_ + (size_t)grow * K + k0 + kc));
                }
            } else {
                v = make_float4(0.f, 0.f, 0.f, 0.f);
            }
            *reinterpret_cast<float4*>(&As[r * SA + kc]) = v;
        }
        #pragma unroll
        for (int i = 0; i < 8; i++) {
            int li = tid + i * 256;
            int kk = li >> 6;
            int nn = li & 63;
            float v = (col0 + nn < N) ? __ldg(&W[(size_t)(k0 + kk) * N + col0 + nn]) : 0.f;
            Bs[nn * SB + kk] = v;
        }
        __syncthreads();

        #pragma unroll
        for (int ks = 0; ks < 32; ks += 8) {
            uint32_t af[2][4];
            #pragma unroll
            for (int mi = 0; mi < 2; mi++) {
                int r = wm * 32 + mi * 16 + gqp;
                af[mi][0] = __float_as_uint(As[r * SA + ks + tig]);
                af[mi][1] = __float_as_uint(As[(r + 8) * SA + ks + tig]);
                af[mi][2] = __float_as_uint(As[r * SA + ks + tig + 4]);
                af[mi][3] = __float_as_uint(As[(r + 8) * SA + ks + tig + 4]);
            }
            uint32_t bf[4][2];
            #pragma unroll
            for (int ni = 0; ni < 4; ni++) {
                int nr = wn * 32 + ni * 8 + gqp;
                bf[ni][0] = __float_as_uint(Bs[nr * SB + ks + tig]);
                bf[ni][1] = __float_as_uint(Bs[nr * SB + ks + tig + 4]);
            }
            #pragma unroll
            for (int mi = 0; mi < 2; mi++)
                #pragma unroll
                for (int ni = 0; ni < 4; ni++)
                    mma_tf32(acc[mi][ni], af[mi], bf[ni]);
        }
        __syncthreads();
    }

    #pragma unroll
    for (int ni = 0; ni < 4; ni++) {
        int cb = col0 + wn * 32 + ni * 8 + 2 * tig;
        float sc0 = 1.f, of0 = 0.f, sc1 = 1.f, of1 = 0.f;
        if (EPI == 1) {
            if (cb < N) {
                float s = p2[cb] * rsqrtf(p5[cb] + BN_EPS);
                sc0 = s; of0 = (p1[cb] - p4[cb]) * s + p3[cb];
            }
            if (cb + 1 < N) {
                float s = p2[cb + 1] * rsqrtf(p5[cb + 1] + BN_EPS);
                sc1 = s; of1 = (p1[cb + 1] - p4[cb + 1]) * s + p3[cb + 1];
            }
        }
        #pragma unroll
        for (int mi = 0; mi < 2; mi++) {
            #pragma unroll
            for (int rr = 0; rr < 2; rr++) {
                int r = row0 + wm * 32 + mi * 16 + gqp + rr * 8;
                if (r >= M) continue;
                float v0 = acc[mi][ni][rr * 2 + 0];
                float v1 = acc[mi][ni][rr * 2 + 1];
                if (EPI == 0) {
                    float dv = p0[r];
                    v0 *= dv; v1 *= dv;
                } else if (EPI == 1) {
                    v0 = fmaxf(v0 * sc0 + of0, 0.f);
                    v1 = fmaxf(v1 * sc1 + of1, 0.f);
                }
                if (OUTH) {
                    __half* C = (__half*)Cv;
                    if (cb + 1 < N)
                        *reinterpret_cast<__half2*>(C + (size_t)r * N + cb) = __floats2half2_rn(v0, v1);
                    else if (cb < N)
                        C[(size_t)r * N + cb] = __float2half_rn(v0);
                } else {
                    float* C = (float*)Cv;
                    if (cb + 1 < N)
                        *reinterpret_cast<float2*>(C + (size_t)r * N + cb) = make_float2(v0, v1);
                    else if (cb < N)
                        C[(size_t)r * N + cb] = v0;
                }
            }
        }
    }
}

// ---------------- launch ----------------------------------------------------
extern "C" void kernel_launch(void* const* d_in, const int* in_sizes, int n_in,
                              void* d_out, int out_size) {
    const float* x   = (const float*)d_in[0];
    const void*  ei  = d_in[1];
    const float* W1  = (const float*)d_in[2];
    const float* b1  = (const float*)d_in[3];
    const float* W2  = (const float*)d_in[4];
    const float* b2  = (const float*)d_in[5];
    const float* W3  = (const float*)d_in[6];
    const float* b3  = (const float*)d_in[7];
    const float* g1  = (const float*)d_in[8];
    const float* bt1 = (const float*)d_in[9];
    const float* rm1 = (const float*)d_in[10];
    const float* rv1 = (const float*)d_in[11];
    const float* g2  = (const float*)d_in[12];
    const float* bt2 = (const float*)d_in[13];
    const float* rm2 = (const float*)d_in[14];
    const float* rv2 = (const float*)d_in[15];
    float* out = (float*)d_out;
    const int E = in_sizes[1] / 2;
    const int n = NN;

    float *pDinv;
    __half *pH1, *pH2, *pHC, *pH3;
    int *pCnt, *pRow, *pCur, *pPerm, *pPart, *pFlag;
    cudaGetSymbolAddress((void**)&pDinv,  g_dinv);
    cudaGetSymbolAddress((void**)&pCnt,   g_cnt);
    cudaGetSymbolAddress((void**)&pRow,   g_rowstart);
    cudaGetSymbolAddress((void**)&pCur,   g_cursor);
    cudaGetSymbolAddress((void**)&pPerm,  g_perm);
    cudaGetSymbolAddress((void**)&pPart,  g_part);
    cudaGetSymbolAddress((void**)&pFlag,  g_is64);
    cudaGetSymbolAddress((void**)&pH1,    g_h1);
    cudaGetSymbolAddress((void**)&pH2,    g_h2);
    cudaGetSymbolAddress((void**)&pHC,    g_hC);
    cudaGetSymbolAddress((void**)&pH3,    g_h3);

    static cudaStream_t s2 = 0;
    static cudaEvent_t evF = 0, evJ = 0;
    if (s2 == 0) {
        if (cudaStreamCreateWithFlags(&s2, cudaStreamNonBlocking) != cudaSuccess) s2 = 0;
        if (s2) {
            cudaEventCreateWithFlags(&evF, cudaEventDisableTiming);
            cudaEventCreateWithFlags(&evJ, cudaEventDisableTiming);
        }
    }
    const bool dual = (s2 != 0);
    cudaStream_t sc = dual ? s2 : (cudaStream_t)0;

    const int T = 256;

    // ---- fork: CSR build on side stream ----
    if (dual) {
        cudaEventRecord(evF, 0);
        cudaStreamWaitEvent(s2, evF, 0);
    }
    detect_k<<<1, 32, 0, sc>>>(ei, pFlag);
    zero_i_k<<<(n + T - 1) / T, T, 0, sc>>>(pCnt, n);
    prep_k<<<(E / 4 + T - 1) / T, T, 0, sc>>>(ei, pCnt, E, pFlag);
    scan1_k<<<NB, SCAN_B, 0, sc>>>(pCnt, pPart, n);
    scan2_k<<<1, 256, 0, sc>>>(pPart, NB);
    scan3_k<<<NB, SCAN_B, 0, sc>>>(pCnt, pPart, pRow, pCur, pDinv, n);
    fill_k<<<(E / 2 + T - 1) / T, T, 0, sc>>>(ei, pCur, pPerm, E, pFlag);
    if (dual) cudaEventRecord(evJ, s2);

    // ---- layer 1 (overlapped with CSR): hs1_raw = x @ W1 -> fp16 ----
    gemm_tf32_k<2, true, false><<<dim3((n + 127) / 128, 1), 256>>>(
        x, W1, pH1, n, H1, F_IN, nullptr, nullptr, nullptr, nullptr, nullptr, nullptr);

    // ---- join ----
    if (dual) cudaStreamWaitEvent(0, evJ, 0);

    // h1 *= dinv[row]
    scale1_k<<<(n * 8 + T - 1) / T, T>>>(pH1, pDinv, n);

    // hs2(fp16) = relu(bn1(agg(h1') + b1)) * dinv
    agg_k<64, 1><<<(n * 32 + T - 1) / T, T>>>(pH1, pH2, pRow, pPerm, pDinv,
                                              b1, g1, bt1, rm1, rv1, n);

    // ---- layer 2: agg2(fp16, reuses g_h1) ----
    agg_k<64, 0><<<(n * 32 + T - 1) / T, T>>>(pH2, pH1, pRow, pPerm, pDinv,
                                              nullptr, nullptr, nullptr, nullptr, nullptr, n);
    // h2(fp16) = relu(bn2(agg2 @ W2 + b2))
    gemm_tf32_k<1, true, true><<<dim3((n + 127) / 128, 2), 256>>>(
        pH1, W2, pHC, n, H2, H1, nullptr, b2, g2, bt2, rm2, rv2);

    // ---- layer 3: hs3(fp16) = (h2 @ W3) * dinv ----
    gemm_tf32_k<0, true, true><<<dim3((n + 127) / 128, 1), 256>>>(
        pHC, W3, pH3, n, NC, H2, pDinv, nullptr, nullptr, nullptr, nullptr, nullptr);

    // agg3 + b3 + log_softmax fused, writes d_out directly
    agg_k<40, 2><<<(n * 32 + T - 1) / T, T>>>(pH3, out, pRow, pPerm, pDinv,
                                              b3, nullptr, nullptr, nullptr, nullptr, n);
}

// round 17
// speedup vs baseline: 1.1167x; 1.0176x over previous
#include <cuda_runtime.h>
#include <cuda_fp16.h>
#include <math.h>
#include <stdint.h>

#define NN    100000
#define EMAX  3200000
#define F_IN  512
#define H1    64
#define H2    128
#define NC    40
#define BN_EPS 1e-5f
#define SCAN_B 512
#define NB    ((NN + SCAN_B - 1) / SCAN_B)

// ---------------- scratch (device globals; no allocation allowed) ----------
__device__ __align__(16) float  g_dinv[NN];
__device__ __align__(16) int    g_cnt[NN];
__device__ __align__(16) int    g_rowstart[NN + 1];
__device__ __align__(16) int    g_cursor[NN];
__device__ __align__(16) int    g_perm[EMAX];
__device__ __align__(16) int    g_part[NB];
__device__ int g_is64;
__device__ __align__(16) __half g_h1[(size_t)NN * 64];   // hs1*dinv / agg2 (fp16)
__device__ __align__(16) __half g_h2[(size_t)NN * 64];   // hs2 (fp16)
__device__ __align__(16) __half g_hC[(size_t)NN * 128];  // h2 (fp16)
__device__ __align__(16) __half g_h3[(size_t)NN * 40];   // hs3 (fp16)

// ---------------- CSR build --------------------------------------------------
__global__ void detect_k(const void* ei, int* flag) {
    if (threadIdx.x == 0) {
        const long long* p = (const long long*)ei;
        int is64 = 1;
        #pragma unroll
        for (int i = 0; i < 32; i++) {
            long long v = p[i];
            if (v < 0 || v >= NN) is64 = 0;
        }
        *flag = is64;
    }
}

__global__ void zero_i_k(int* p, int n) {
    int i = blockIdx.x * blockDim.x + threadIdx.x;
    if (i < n) p[i] = 0;
}

// count in-degree: 4 edges per thread (vectorized when E aligned)
__global__ void prep_k(const void* eiv, int* __restrict__ cnt, int E,
                       const int* __restrict__ flag) {
    int t = blockIdx.x * blockDim.x + threadIdx.x;
    int e0 = t * 4;
    if (e0 >= E) return;
    int d[4];
    int m = min(4, E - e0);
    if (*flag) {
        const long long* p64 = (const long long*)eiv + (size_t)E;
        if (m == 4 && ((E & 1) == 0)) {
            longlong2 a = __ldg(reinterpret_cast<const longlong2*>(p64 + e0));
            longlong2 b = __ldg(reinterpret_cast<const longlong2*>(p64 + e0 + 2));
            d[0] = (int)a.x; d[1] = (int)a.y; d[2] = (int)b.x; d[3] = (int)b.y;
        } else {
            for (int i = 0; i < m; i++) d[i] = (int)__ldg(&p64[e0 + i]);
        }
    } else {
        const int* p32 = (const int*)eiv + (size_t)E;
        if (m == 4 && ((E & 3) == 0)) {
            int4 a = __ldg(reinterpret_cast<const int4*>(p32 + e0));
            d[0] = a.x; d[1] = a.y; d[2] = a.z; d[3] = a.w;
        } else {
            for (int i = 0; i < m; i++) d[i] = __ldg(&p32[e0 + i]);
        }
    }
    #pragma unroll
    for (int i = 0; i < 4; i++) {
        if (i < m) {
            int dd = min(max(d[i], 0), NN - 1);
            atomicAdd(&cnt[dd], 1);
        }
    }
}

__global__ void scan1_k(const int* __restrict__ cnt, int* __restrict__ part, int n) {
    __shared__ int sh[SCAN_B];
    int i = blockIdx.x * SCAN_B + threadIdx.x;
    sh[threadIdx.x] = (i < n) ? cnt[i] : 0;
    __syncthreads();
    #pragma unroll
    for (int o = SCAN_B / 2; o > 0; o >>= 1) {
        if (threadIdx.x < o) sh[threadIdx.x] += sh[threadIdx.x + o];
        __syncthreads();
    }
    if (threadIdx.x == 0) part[blockIdx.x] = sh[0];
}

__global__ void scan2_k(int* part, int nb) {
    __shared__ int sh[256];
    int v = (threadIdx.x < nb) ? part[threadIdx.x] : 0;
    sh[threadIdx.x] = v;
    __syncthreads();
    #pragma unroll
    for (int o = 1; o < 256; o <<= 1) {
        int t = (threadIdx.x >= o) ? sh[threadIdx.x - o] : 0;
        __syncthreads();
        sh[threadIdx.x] += t;
        __syncthreads();
    }
    if (threadIdx.x < nb) part[threadIdx.x] = sh[threadIdx.x] - v;  // exclusive
}

__global__ void scan3_k(const int* __restrict__ cnt, const int* __restrict__ part,
                        int* __restrict__ rowstart, int* __restrict__ cursor,
                        float* __restrict__ dinv, int n) {
    __shared__ int sh[SCAN_B];
    int i = blockIdx.x * SCAN_B + threadIdx.x;
    int v = (i < n) ? cnt[i] : 0;
    sh[threadIdx.x] = v;
    __syncthreads();
    #pragma unroll
    for (int o = 1; o < SCAN_B; o <<= 1) {
        int t = (threadIdx.x >= o) ? sh[threadIdx.x - o] : 0;
        __syncthreads();
        sh[threadIdx.x] += t;
        __syncthreads();
    }
    int incl = sh[threadIdx.x];
    int off = part[blockIdx.x];
    if (i < n) {
        int excl = off + incl - v;
        rowstart[i] = excl;
        cursor[i] = excl;
        dinv[i] = rsqrtf((float)v + 1.0f);   // +1 self-loop
        if (i == n - 1) rowstart[n] = off + incl;
    }
}

// place src into CSR perm slots: 2 edges per thread (vectorized when aligned)
__global__ void fill_k(const void* eiv, int* __restrict__ cursor,
                       int* __restrict__ perm, int E,
                       const int* __restrict__ flag) {
    int t = blockIdx.x * blockDim.x + threadIdx.x;
    int e0 = t * 2;
    if (e0 >= E) return;
    int s[2], d[2];
    int m = min(2, E - e0);
    if (*flag) {
        const long long* p64 = (const long long*)eiv;
        if (m == 2 && ((E & 1) == 0)) {
            longlong2 a = __ldg(reinterpret_cast<const longlong2*>(p64 + e0));
            longlong2 b = __ldg(reinterpret_cast<const longlong2*>(p64 + (size_t)E + e0));
            s[0] = (int)a.x; s[1] = (int)a.y;
            d[0] = (int)b.x; d[1] = (int)b.y;
        } else {
            for (int i = 0; i < m; i++) {
                s[i] = (int)__ldg(&p64[e0 + i]);
                d[i] = (int)__ldg(&p64[(size_t)E + e0 + i]);
            }
        }
    } else {
        const int* p32 = (const int*)eiv;
        if (m == 2 && ((E & 1) == 0)) {
            int2 a = __ldg(reinterpret_cast<const int2*>(p32 + e0));
            int2 b = __ldg(reinterpret_cast<const int2*>(p32 + (size_t)E + e0));
            s[0] = a.x; s[1] = a.y;
            d[0] = b.x; d[1] = b.y;
        } else {
            for (int i = 0; i < m; i++) {
                s[i] = __ldg(&p32[e0 + i]);
                d[i] = __ldg(&p32[(size_t)E + e0 + i]);
            }
        }
    }
    #pragma unroll
    for (int i = 0; i < 2; i++) {
        if (i < m) {
            int ss = min(max(s[i], 0), NN - 1);
            int dd = min(max(d[i], 0), NN - 1);
            int pos = atomicAdd(&cursor[dd], 1);
            pos = min(max(pos, 0), E - 1);
            perm[pos] = ss;
        }
    }
}

// ---------------- h1 *= dinv[row]  (fp16 storage, fp32 math) ----------------
__global__ void scale1_k(__half* __restrict__ h, const float* __restrict__ dinv, int n) {
    int t = blockIdx.x * blockDim.x + threadIdx.x;       // n*8 threads
    if (t >= n * 8) return;
    int node = t >> 3;
    int seg  = t & 7;
    float dv = dinv[node];
    uint4 u = *reinterpret_cast<uint4*>(h + (size_t)node * 64 + seg * 8);
    uint32_t* w = &u.x;
    #pragma unroll
    for (int i = 0; i < 4; i++) {
        float2 f = __half22float2(*reinterpret_cast<__half2*>(&w[i]));
        __half2 r = __floats2half2_rn(f.x * dv, f.y * dv);
        w[i] = *reinterpret_cast<uint32_t*>(&r);
    }
    *reinterpret_cast<uint4*>(h + (size_t)node * 64 + seg * 8) = u;
}

// ---------------- warp-per-node gather aggregation (fp16 in, fp32 accum) ----
__device__ __forceinline__ float4 ld_h4(const __half* p) {
    uint2 u = *reinterpret_cast<const uint2*>(p);
    float2 f01 = __half22float2(*reinterpret_cast<const __half2*>(&u.x));
    float2 f23 = __half22float2(*reinterpret_cast<const __half2*>(&u.y));
    return make_float4(f01.x, f01.y, f23.x, f23.y);
}

// EPI 0: out(fp16) = (sum + own) * dinv
// EPI 1: out(fp16) = relu(bn((sum + own)*dinv + b)) * dinv
// EPI 2: out(fp32) = log_softmax((sum + own)*dinv + b)   (D == 40)
// Processes nodes [base, base+cnt).
template <int D, int EPI>
__global__ void __launch_bounds__(256) agg_k(
    const __half* __restrict__ hs, void* __restrict__ outv,
    const int* __restrict__ rowstart, const int* __restrict__ perm,
    const float* __restrict__ dinv,
    const float* __restrict__ b, const float* __restrict__ g,
    const float* __restrict__ bt, const float* __restrict__ rm,
    const float* __restrict__ rv, int base, int cnt) {
    const int warp = (blockIdx.x * blockDim.x + threadIdx.x) >> 5;
    const int lane = threadIdx.x & 31;
    if (warp >= cnt) return;
    const int node = base + warp;
    const int half = lane >> 4;          // 0 or 1
    const int hl   = lane & 15;
    const int c    = hl * 4;
    const bool act = (c < D);
    const int start = rowstart[node];
    const int end   = rowstart[node + 1];

    float sx = 0.f, sy = 0.f, sz = 0.f, sw = 0.f;
    int j = start + half;
    for (; j + 2 < end; j += 4) {
        int s0 = __ldg(&perm[j]);
        int s1 = __ldg(&perm[j + 2]);
        if (act) {
            float4 v0 = ld_h4(hs + (size_t)s0 * D + c);
            float4 v1 = ld_h4(hs + (size_t)s1 * D + c);
            sx += v0.x + v1.x;
            sy += v0.y + v1.y;
            sz += v0.z + v1.z;
            sw += v0.w + v1.w;
        }
    }
    if (j < end) {
        int s0 = __ldg(&perm[j]);
        if (act) {
            float4 v0 = ld_h4(hs + (size_t)s0 * D + c);
            sx += v0.x; sy += v0.y; sz += v0.z; sw += v0.w;
        }
    }
    sx += __shfl_xor_sync(0xffffffffu, sx, 16);
    sy += __shfl_xor_sync(0xffffffffu, sy, 16);
    sz += __shfl_xor_sync(0xffffffffu, sz, 16);
    sw += __shfl_xor_sync(0xffffffffu, sw, 16);

    const float dv = dinv[node];
    float4 own = act ? ld_h4(hs + (size_t)node * D + c)
                     : make_float4(0.f, 0.f, 0.f, 0.f);
    float vx = (sx + own.x) * dv;
    float vy = (sy + own.y) * dv;
    float vz = (sz + own.z) * dv;
    float vw = (sw + own.w) * dv;

    if (EPI == 1) {
        if (half == 0 && act) {
            float4 bb  = __ldg(reinterpret_cast<const float4*>(b + c));
            float4 gg  = __ldg(reinterpret_cast<const float4*>(g + c));
            float4 bt4 = __ldg(reinterpret_cast<const float4*>(bt + c));
            float4 rm4 = __ldg(reinterpret_cast<const float4*>(rm + c));
            float4 rv4 = __ldg(reinterpret_cast<const float4*>(rv + c));
            vx = fmaxf((vx + bb.x - rm4.x) * (gg.x * rsqrtf(rv4.x + BN_EPS)) + bt4.x, 0.f) * dv;
            vy = fmaxf((vy + bb.y - rm4.y) * (gg.y * rsqrtf(rv4.y + BN_EPS)) + bt4.y, 0.f) * dv;
            vz = fmaxf((vz + bb.z - rm4.z) * (gg.z * rsqrtf(rv4.z + BN_EPS)) + bt4.z, 0.f) * dv;
            vw = fmaxf((vw + bb.w - rm4.w) * (gg.w * rsqrtf(rv4.w + BN_EPS)) + bt4.w, 0.f) * dv;
            __half2 o01 = __floats2half2_rn(vx, vy);
            __half2 o23 = __floats2half2_rn(vz, vw);
            uint2 u;
            u.x = *reinterpret_cast<uint32_t*>(&o01);
            u.y = *reinterpret_cast<uint32_t*>(&o23);
            *reinterpret_cast<uint2*>((__half*)outv + (size_t)node * D + c) = u;
        }
    } else if (EPI == 0) {
        if (half == 0 && act) {
            __half2 o01 = __floats2half2_rn(vx, vy);
            __half2 o23 = __floats2half2_rn(vz, vw);
            uint2 u;
            u.x = *reinterpret_cast<uint32_t*>(&o01);
            u.y = *reinterpret_cast<uint32_t*>(&o23);
            *reinterpret_cast<uint2*>((__half*)outv + (size_t)node * D + c) = u;
        }
    } else {
        float4 bb = act ? __ldg(reinterpret_cast<const float4*>(b + c))
                        : make_float4(0.f, 0.f, 0.f, 0.f);
        vx += bb.x; vy += bb.y; vz += bb.z; vw += bb.w;
        float m = act ? fmaxf(fmaxf(vx, vy), fmaxf(vz, vw)) : -INFINITY;
        #pragma unroll
        for (int o = 8; o; o >>= 1) m = fmaxf(m, __shfl_xor_sync(0xffffffffu, m, o));
        float es = act ? (expf(vx - m) + expf(vy - m) + expf(vz - m) + expf(vw - m)) : 0.f;
        #pragma unroll
        for (int o = 8; o; o >>= 1) es += __shfl_xor_sync(0xffffffffu, es, o);
        float lse = m + logf(es);
        if (half == 0 && act)
            *reinterpret_cast<float4*>((float*)outv + (size_t)node * D + c) =
                make_float4(vx - lse, vy - lse, vz - lse, vw - lse);
    }
}

// ---------------- tensor-core GEMM: tf32 single-pass, fp32 accum ------------
// INH: A buffer is fp16 (converted to fp32 while staging into smem).
// EPI 0: C = acc * dinv[row]   EPI 1: C = relu(bn(acc + bias))   EPI 2: raw
// OUTH: write __half output, else fp32.
__device__ __forceinline__ void mma_tf32(float* c, const uint32_t* a, const uint32_t* b) {
    asm volatile(
        "mma.sync.aligned.m16n8k8.row.col.f32.tf32.tf32.f32 "
        "{%0,%1,%2,%3}, {%4,%5,%6,%7}, {%8,%9}, {%0,%1,%2,%3};"
        : "+f"(c[0]), "+f"(c[1]), "+f"(c[2]), "+f"(c[3])
        : "r"(a[0]), "r"(a[1]), "r"(a[2]), "r"(a[3]), "r"(b[0]), "r"(b[1]));
}

template <int EPI, bool OUTH, bool INH>
__global__ void __launch_bounds__(256) gemm_tf32_k(
    const void* __restrict__ Av, const float* __restrict__ W,
    void* __restrict__ Cv, int M, int N, int K,
    const float* __restrict__ p0, const float* __restrict__ p1,
    const float* __restrict__ p2, const float* __restrict__ p3,
    const float* __restrict__ p4, const float* __restrict__ p5) {
    constexpr int SA = 36;
    constexpr int SB = 36;
    __shared__ __align__(16) float As[128 * SA];
    __shared__ __align__(16) float Bs[64 * SB];

    const int tid  = threadIdx.x;
    const int lane = tid & 31;
    const int warp = tid >> 5;
    const int gqp  = lane >> 2;
    const int tig  = lane & 3;
    const int wm   = warp >> 1;
    const int wn   = warp & 1;
    const int row0 = blockIdx.x * 128;
    const int col0 = blockIdx.y * 64;

    float acc[2][4][4];
    #pragma unroll
    for (int mi = 0; mi < 2; mi++)
        #pragma unroll
        for (int ni = 0; ni < 4; ni++)
            #pragma unroll
            for (int q = 0; q < 4; q++) acc[mi][ni][q] = 0.f;

    for (int k0 = 0; k0 < K; k0 += 32) {
        #pragma unroll
        for (int i = 0; i < 4; i++) {
            int li = tid + i * 256;
            int r  = li >> 3;
            int kc = (li & 7) * 4;
            int grow = row0 + r;
            float4 v;
            if (grow < M) {
                if (INH) {
                    const __half* Ah_ = (const __half*)Av;
                    uint2 u = __ldg(reinterpret_cast<const uint2*>(
                        Ah_ + (size_t)grow * K + k0 + kc));
                    float2 f01 = __half22float2(*reinterpret_cast<const __half2*>(&u.x));
                    float2 f23 = __half22float2(*reinterpret_cast<const __half2*>(&u.y));
                    v = make_float4(f01.x, f01.y, f23.x, f23.y);
                } else {
                    const float* Af_ = (const float*)Av;
                    v = __ldg(reinterpret_cast<const float4*>(
                        Af_ + (size_t)grow * K + k0 + kc));
                }
            } else {
                v = make_float4(0.f, 0.f, 0.f, 0.f);
            }
            *reinterpret_cast<float4*>(&As[r * SA + kc]) = v;
        }
        #pragma unroll
        for (int i = 0; i < 8; i++) {
            int li = tid + i * 256;
            int kk = li >> 6;
            int nn = li & 63;
            float v = (col0 + nn < N) ? __ldg(&W[(size_t)(k0 + kk) * N + col0 + nn]) : 0.f;
            Bs[nn * SB + kk] = v;
        }
        __syncthreads();

        #pragma unroll
        for (int ks = 0; ks < 32; ks += 8) {
            uint32_t af[2][4];
            #pragma unroll
            for (int mi = 0; mi < 2; mi++) {
                int r = wm * 32 + mi * 16 + gqp;
                af[mi][0] = __float_as_uint(As[r * SA + ks + tig]);
                af[mi][1] = __float_as_uint(As[(r + 8) * SA + ks + tig]);
                af[mi][2] = __float_as_uint(As[r * SA + ks + tig + 4]);
                af[mi][3] = __float_as_uint(As[(r + 8) * SA + ks + tig + 4]);
            }
            uint32_t bf[4][2];
            #pragma unroll
            for (int ni = 0; ni < 4; ni++) {
                int nr = wn * 32 + ni * 8 + gqp;
                bf[ni][0] = __float_as_uint(Bs[nr * SB + ks + tig]);
                bf[ni][1] = __float_as_uint(Bs[nr * SB + ks + tig + 4]);
            }
            #pragma unroll
            for (int mi = 0; mi < 2; mi++)
                #pragma unroll
                for (int ni = 0; ni < 4; ni++)
                    mma_tf32(acc[mi][ni], af[mi], bf[ni]);
        }
        __syncthreads();
    }

    #pragma unroll
    for (int ni = 0; ni < 4; ni++) {
        int cb = col0 + wn * 32 + ni * 8 + 2 * tig;
        float sc0 = 1.f, of0 = 0.f, sc1 = 1.f, of1 = 0.f;
        if (EPI == 1) {
            if (cb < N) {
                float s = p2[cb] * rsqrtf(p5[cb] + BN_EPS);
                sc0 = s; of0 = (p1[cb] - p4[cb]) * s + p3[cb];
            }
            if (cb + 1 < N) {
                float s = p2[cb + 1] * rsqrtf(p5[cb + 1] + BN_EPS);
                sc1 = s; of1 = (p1[cb + 1] - p4[cb + 1]) * s + p3[cb + 1];
            }
        }
        #pragma unroll
        for (int mi = 0; mi < 2; mi++) {
            #pragma unroll
            for (int rr = 0; rr < 2; rr++) {
                int r = row0 + wm * 32 + mi * 16 + gqp + rr * 8;
                if (r >= M) continue;
                float v0 = acc[mi][ni][rr * 2 + 0];
                float v1 = acc[mi][ni][rr * 2 + 1];
                if (EPI == 0) {
                    float dv = p0[r];
                    v0 *= dv; v1 *= dv;
                } else if (EPI == 1) {
                    v0 = fmaxf(v0 * sc0 + of0, 0.f);
                    v1 = fmaxf(v1 * sc1 + of1, 0.f);
                }
                if (OUTH) {
                    __half* C = (__half*)Cv;
                    if (cb + 1 < N)
                        *reinterpret_cast<__half2*>(C + (size_t)r * N + cb) = __floats2half2_rn(v0, v1);
                    else if (cb < N)
                        C[(size_t)r * N + cb] = __float2half_rn(v0);
                } else {
                    float* C = (float*)Cv;
                    if (cb + 1 < N)
                        *reinterpret_cast<float2*>(C + (size_t)r * N + cb) = make_float2(v0, v1);
                    else if (cb < N)
                        C[(size_t)r * N + cb] = v0;
                }
            }
        }
    }
}

// ---------------- launch ----------------------------------------------------
extern "C" void kernel_launch(void* const* d_in, const int* in_sizes, int n_in,
                              void* d_out, int out_size) {
    const float* x   = (const float*)d_in[0];
    const void*  ei  = d_in[1];
    const float* W1  = (const float*)d_in[2];
    const float* b1  = (const float*)d_in[3];
    const float* W2  = (const float*)d_in[4];
    const float* b2  = (const float*)d_in[5];
    const float* W3  = (const float*)d_in[6];
    const float* b3  = (const float*)d_in[7];
    const float* g1  = (const float*)d_in[8];
    const float* bt1 = (const float*)d_in[9];
    const float* rm1 = (const float*)d_in[10];
    const float* rv1 = (const float*)d_in[11];
    const float* g2  = (const float*)d_in[12];
    const float* bt2 = (const float*)d_in[13];
    const float* rm2 = (const float*)d_in[14];
    const float* rv2 = (const float*)d_in[15];
    float* out = (float*)d_out;
    const int E = in_sizes[1] / 2;
    const int n = NN;

    float *pDinv;
    __half *pH1, *pH2, *pHC, *pH3;
    int *pCnt, *pRow, *pCur, *pPerm, *pPart, *pFlag;
    cudaGetSymbolAddress((void**)&pDinv,  g_dinv);
    cudaGetSymbolAddress((void**)&pCnt,   g_cnt);
    cudaGetSymbolAddress((void**)&pRow,   g_rowstart);
    cudaGetSymbolAddress((void**)&pCur,   g_cursor);
    cudaGetSymbolAddress((void**)&pPerm,  g_perm);
    cudaGetSymbolAddress((void**)&pPart,  g_part);
    cudaGetSymbolAddress((void**)&pFlag,  g_is64);
    cudaGetSymbolAddress((void**)&pH1,    g_h1);
    cudaGetSymbolAddress((void**)&pH2,    g_h2);
    cudaGetSymbolAddress((void**)&pHC,    g_hC);
    cudaGetSymbolAddress((void**)&pH3,    g_h3);

    static cudaStream_t s2 = 0;
    static cudaEvent_t evF = 0, evD = 0, evJ = 0, evG = 0, evB = 0;
    if (s2 == 0) {
        if (cudaStreamCreateWithFlags(&s2, cudaStreamNonBlocking) != cudaSuccess) s2 = 0;
        if (s2) {
            cudaEventCreateWithFlags(&evF, cudaEventDisableTiming);
            cudaEventCreateWithFlags(&evD, cudaEventDisableTiming);
            cudaEventCreateWithFlags(&evJ, cudaEventDisableTiming);
            cudaEventCreateWithFlags(&evG, cudaEventDisableTiming);
            cudaEventCreateWithFlags(&evB, cudaEventDisableTiming);
        }
    }
    const bool dual = (s2 != 0);
    cudaStream_t sc = dual ? s2 : (cudaStream_t)0;

    const int T = 256;
    // middle-section row split (chunk A rows [0,HA), chunk B rows [HA,n))
    const int HA = dual ? 50048 : n;          // multiple of 128
    const int HB = n - HA;

    // ---- fork: CSR build on side stream ----
    if (dual) {
        cudaEventRecord(evF, 0);
        cudaStreamWaitEvent(s2, evF, 0);
    }
    detect_k<<<1, 32, 0, sc>>>(ei, pFlag);
    zero_i_k<<<(n + T - 1) / T, T, 0, sc>>>(pCnt, n);
    prep_k<<<(E / 4 + T - 1) / T, T, 0, sc>>>(ei, pCnt, E, pFlag);
    scan1_k<<<NB, SCAN_B, 0, sc>>>(pCnt, pPart, n);
    scan2_k<<<1, 256, 0, sc>>>(pPart, NB);
    scan3_k<<<NB, SCAN_B, 0, sc>>>(pCnt, pPart, pRow, pCur, pDinv, n);
    if (dual) cudaEventRecord(evD, s2);        // dinv ready
    fill_k<<<(E / 2 + T - 1) / T, T, 0, sc>>>(ei, pCur, pPerm, E, pFlag);
    if (dual) cudaEventRecord(evJ, s2);        // CSR fully ready

    // ---- layer 1 (overlapped with CSR): hs1_raw = x @ W1 -> fp16 ----
    gemm_tf32_k<2, true, false><<<dim3((n + 127) / 128, 1), 256>>>(
        x, W1, pH1, n, H1, F_IN, nullptr, nullptr, nullptr, nullptr, nullptr, nullptr);

    // ---- scale1 overlaps fill_k: needs only gemm1 (stream order) + dinv ----
    if (dual) cudaStreamWaitEvent(0, evD, 0);
    scale1_k<<<(n * 8 + T - 1) / T, T>>>(pH1, pDinv, n);

    // ---- join: perm ready ----
    if (dual) cudaStreamWaitEvent(0, evJ, 0);

    // hs2(fp16) = relu(bn1(agg(h1') + b1)) * dinv   (full range)
    agg_k<64, 1><<<(n * 32 + T - 1) / T, T>>>(pH1, pH2, pRow, pPerm, pDinv,
                                              b1, g1, bt1, rm1, rv1, 0, n);
    if (dual) cudaEventRecord(evG, 0);         // hs2 ready

    // ---- middle section: two independent row-chunk chains ----
    // chain A on default stream: rows [0, HA)
    agg_k<64, 0><<<(HA * 32 + T - 1) / T, T>>>(pH2, pH1, pRow, pPerm, pDinv,
                                               nullptr, nullptr, nullptr, nullptr, nullptr, 0, HA);
    gemm_tf32_k<1, true, true><<<dim3((HA + 127) / 128, 2), 256>>>(
        pH1, W2, pHC, HA, H2, H1, nullptr, b2, g2, bt2, rm2, rv2);
    gemm_tf32_k<0, true, true><<<dim3((HA + 127) / 128, 1), 256>>>(
        pHC, W3, pH3, HA, NC, H2, pDinv, nullptr, nullptr, nullptr, nullptr, nullptr);

    if (dual) {
        // chain B on s2: rows [HA, n)
        cudaStreamWaitEvent(s2, evG, 0);
        agg_k<64, 0><<<(HB * 32 + T - 1) / T, T, 0, s2>>>(
            pH2, pH1, pRow, pPerm, pDinv,
            nullptr, nullptr, nullptr, nullptr, nullptr, HA, HB);
        gemm_tf32_k<1, true, true><<<dim3((HB + 127) / 128, 2), 256, 0, s2>>>(
            pH1 + (size_t)HA * H1, W2, pHC + (size_t)HA * H2, HB, H2, H1,
            nullptr, b2, g2, bt2, rm2, rv2);
        gemm_tf32_k<0, true, true><<<dim3((HB + 127) / 128, 1), 256, 0, s2>>>(
            pHC + (size_t)HA * H2, W3, pH3 + (size_t)HA * NC, HB, NC, H2,
            pDinv + HA, nullptr, nullptr, nullptr, nullptr, nullptr);
        cudaEventRecord(evB, s2);
        cudaStreamWaitEvent(0, evB, 0);
    }

    // agg3 + b3 + log_softmax fused, writes d_out directly (needs all h3)
    agg_k<40, 2><<<(n * 32 + T - 1) / T, T>>>(pH3, out, pRow, pPerm, pDinv,
                                              b3, nullptr, nullptr, nullptr, nullptr, 0, n);
}